// round 1
// baseline (speedup 1.0000x reference)
#include <cuda_runtime.h>
#include <cstdint>

// ---------------------------------------------------------------------------
// Problem constants
//   x,y: (8,1024,512) -> flat (8192,512). 64 attention "instances": instance
//   i = h*8+b' uses contiguous slab [i*65536, (i+1)*65536) of each projection
//   viewed as (1024,64). Output slabs are contiguous in the same way.
// ---------------------------------------------------------------------------
#define NORMF 0.04419417382415922f   // 1/sqrt(512)

static __device__ float g_Qp[8192 * 512];
static __device__ float g_Kp[8192 * 512];
static __device__ float g_Vp[8192 * 512];
static __device__ float g_AO[8192 * 512];
static __device__ float g_S[67108864];        // 64 * 1024 * 1024 scores (268MB)
static __device__ float4 g_stats[64 * 1024];  // per score-row: mean, max, 1/Z

// Packed f32x2 FMA (Blackwell): 2 FMAs per instruction, full fp32 rate.
#define FMA2(d, a, b, c) \
    asm("fma.rn.f32x2 %0, %1, %2, %3;" : "=l"(d) : "l"(a), "l"(b), "l"(c))
#define PACK2(d, x) \
    asm("mov.b64 %0, {%1, %1};" : "=l"(d) : "r"(x))
#define UNPK2(lo, hi, d) \
    asm("mov.b64 {%0, %1}, %2;" : "=r"(lo), "=r"(hi) : "l"(d))

// ---------------------------------------------------------------------------
// 128x128 tile fp32 GEMM body (single-buffered, BK=8, 256 thr, 8x8/thread,
// packed f32x2 inner product). C = A(MxK) @ W(KxN) + bias. All dims multiples.
// ---------------------------------------------------------------------------
__device__ __forceinline__ void gemm128x128(
    const float* __restrict__ A, const float* __restrict__ W,
    const float* __restrict__ bias, float* __restrict__ C, int N, int K)
{
    __shared__ __align__(16) float As[8][128];
    __shared__ __align__(16) float Bs[8][128];
    int tid = threadIdx.x;
    int row0 = blockIdx.y * 128;
    int col0 = blockIdx.x * 128;
    int ty = tid >> 4, tx = tid & 15;

    uint64_t acc[8][4];
#pragma unroll
    for (int i = 0; i < 8; i++)
#pragma unroll
        for (int j = 0; j < 4; j++) acc[i][j] = 0ull;

    int ar = tid >> 1, ac = (tid & 1) * 4;
    int br = tid >> 5, bc = (tid & 31) * 4;
    const float* Aptr = A + (size_t)(row0 + ar) * K + ac;
    const float* Wptr = W + (size_t)br * N + col0 + bc;

    for (int k0 = 0; k0 < K; k0 += 8) {
        float4 av = *(const float4*)(Aptr + k0);
        float4 bv = *(const float4*)(Wptr + (size_t)k0 * N);
        __syncthreads();
        As[ac + 0][ar] = av.x; As[ac + 1][ar] = av.y;
        As[ac + 2][ar] = av.z; As[ac + 3][ar] = av.w;
        *(float4*)&Bs[br][bc] = bv;
        __syncthreads();
#pragma unroll
        for (int kk = 0; kk < 8; kk++) {
            float4 a0 = *(const float4*)&As[kk][ty * 8];
            float4 a1 = *(const float4*)&As[kk][ty * 8 + 4];
            ulonglong2 b0 = *(const ulonglong2*)&Bs[kk][tx * 8];
            ulonglong2 b1 = *(const ulonglong2*)&Bs[kk][tx * 8 + 4];
            uint64_t bp[4] = {b0.x, b0.y, b1.x, b1.y};
            float af[8] = {a0.x, a0.y, a0.z, a0.w, a1.x, a1.y, a1.z, a1.w};
#pragma unroll
            for (int i = 0; i < 8; i++) {
                uint64_t ap;
                PACK2(ap, __float_as_uint(af[i]));
#pragma unroll
                for (int j = 0; j < 4; j++) FMA2(acc[i][j], ap, bp[j], acc[i][j]);
            }
        }
    }

#pragma unroll
    for (int i = 0; i < 8; i++) {
        int r = row0 + ty * 8 + i;
#pragma unroll
        for (int j = 0; j < 4; j++) {
            uint32_t lo, hi;
            UNPK2(lo, hi, acc[i][j]);
            int c = col0 + tx * 8 + j * 2;
            float2 o;
            o.x = __uint_as_float(lo) + bias[c];
            o.y = __uint_as_float(hi) + bias[c + 1];
            *(float2*)(C + (size_t)r * N + c) = o;
        }
    }
}

// ---------------------------------------------------------------------------
// Kernel 1: fused Q/K/V projections (z selects which one)
// ---------------------------------------------------------------------------
__global__ __launch_bounds__(256) void proj_kernel(
    const float* __restrict__ x, const float* __restrict__ y,
    const float* __restrict__ qw, const float* __restrict__ qb,
    const float* __restrict__ kw, const float* __restrict__ kb,
    const float* __restrict__ vw, const float* __restrict__ vb)
{
    const float* A; const float* W; const float* b; float* C;
    if (blockIdx.z == 0)      { A = x; W = qw; b = qb; C = g_Qp; }
    else if (blockIdx.z == 1) { A = y; W = kw; b = kb; C = g_Kp; }
    else                      { A = y; W = vw; b = vb; C = g_Vp; }
    gemm128x128(A, W, b, C, 512, 512);
}

// ---------------------------------------------------------------------------
// Kernel 2: scores S = (Q @ K^T) * NORM per instance (1024x1024x64)
// ---------------------------------------------------------------------------
__global__ __launch_bounds__(256) void qk_kernel()
{
    __shared__ __align__(16) float As[8][128];
    __shared__ __align__(16) float Bs[8][128];
    int tid = threadIdx.x;
    int inst = blockIdx.z;
    const float* Q  = g_Qp + (size_t)inst * 65536;
    const float* Kc = g_Kp + (size_t)inst * 65536;
    float* Sout = g_S + ((size_t)inst << 20);
    int row0 = blockIdx.y * 128;
    int col0 = blockIdx.x * 128;
    int ty = tid >> 4, tx = tid & 15;

    uint64_t acc[8][4];
#pragma unroll
    for (int i = 0; i < 8; i++)
#pragma unroll
        for (int j = 0; j < 4; j++) acc[i][j] = 0ull;

    int ar = tid >> 1, ac = (tid & 1) * 4;

    for (int k0 = 0; k0 < 64; k0 += 8) {
        float4 av = *(const float4*)(Q  + (size_t)(row0 + ar) * 64 + k0 + ac);
        float4 bv = *(const float4*)(Kc + (size_t)(col0 + ar) * 64 + k0 + ac);
        __syncthreads();
        As[ac + 0][ar] = av.x; As[ac + 1][ar] = av.y;
        As[ac + 2][ar] = av.z; As[ac + 3][ar] = av.w;
        Bs[ac + 0][ar] = bv.x; Bs[ac + 1][ar] = bv.y;
        Bs[ac + 2][ar] = bv.z; Bs[ac + 3][ar] = bv.w;
        __syncthreads();
#pragma unroll
        for (int kk = 0; kk < 8; kk++) {
            float4 a0 = *(const float4*)&As[kk][ty * 8];
            float4 a1 = *(const float4*)&As[kk][ty * 8 + 4];
            ulonglong2 b0 = *(const ulonglong2*)&Bs[kk][tx * 8];
            ulonglong2 b1 = *(const ulonglong2*)&Bs[kk][tx * 8 + 4];
            uint64_t bp[4] = {b0.x, b0.y, b1.x, b1.y};
            float af[8] = {a0.x, a0.y, a0.z, a0.w, a1.x, a1.y, a1.z, a1.w};
#pragma unroll
            for (int i = 0; i < 8; i++) {
                uint64_t ap;
                PACK2(ap, __float_as_uint(af[i]));
#pragma unroll
                for (int j = 0; j < 4; j++) FMA2(acc[i][j], ap, bp[j], acc[i][j]);
            }
        }
    }

#pragma unroll
    for (int i = 0; i < 8; i++) {
        size_t r = (size_t)(row0 + ty * 8 + i) * 1024;
#pragma unroll
        for (int j = 0; j < 4; j++) {
            uint32_t lo, hi;
            UNPK2(lo, hi, acc[i][j]);
            float2 o;
            o.x = __uint_as_float(lo) * NORMF;
            o.y = __uint_as_float(hi) * NORMF;
            *(float2*)(Sout + r + col0 + tx * 8 + j * 2) = o;
        }
    }
}

// ---------------------------------------------------------------------------
// Kernel 3: per-row stats — mean, max, 1/Z where Z = sum_{s>mean} exp(s-max)
// One block per score row (65536 rows of 1024 floats).
// ---------------------------------------------------------------------------
__global__ __launch_bounds__(256) void stats_kernel()
{
    int row = blockIdx.x;
    const float4* s = (const float4*)(g_S + ((size_t)row << 10));
    int tid = threadIdx.x;
    float4 v = s[tid];
    float lsum = (v.x + v.y) + (v.z + v.w);
    float lmax = fmaxf(fmaxf(v.x, v.y), fmaxf(v.z, v.w));
#pragma unroll
    for (int o = 16; o; o >>= 1) {
        lsum += __shfl_xor_sync(0xffffffffu, lsum, o);
        lmax = fmaxf(lmax, __shfl_xor_sync(0xffffffffu, lmax, o));
    }
    __shared__ float ssum[8], smaxs[8], szs[8];
    int wid = tid >> 5, lid = tid & 31;
    if (!lid) { ssum[wid] = lsum; smaxs[wid] = lmax; }
    __syncthreads();
    float tsum = 0.f, tmax = -1e30f;
#pragma unroll
    for (int i = 0; i < 8; i++) {
        tsum += ssum[i];
        tmax = fmaxf(tmax, smaxs[i]);
    }
    float mean = tsum * (1.0f / 1024.0f);
    float z = 0.f;
    z += (v.x > mean) ? __expf(v.x - tmax) : 0.f;
    z += (v.y > mean) ? __expf(v.y - tmax) : 0.f;
    z += (v.z > mean) ? __expf(v.z - tmax) : 0.f;
    z += (v.w > mean) ? __expf(v.w - tmax) : 0.f;
#pragma unroll
    for (int o = 16; o; o >>= 1) z += __shfl_xor_sync(0xffffffffu, z, o);
    if (!lid) szs[wid] = z;
    __syncthreads();
    if (!tid) {
        float tz = 0.f;
#pragma unroll
        for (int i = 0; i < 8; i++) tz += szs[i];
        g_stats[row] = make_float4(mean, tmax, 1.0f / tz, 0.f);
    }
}

// ---------------------------------------------------------------------------
// Kernel 4: O = softmax_masked(S) @ V per instance. The softmax transform is
// applied on the A-tile global load (each score read exactly once).
// Tile: 128(M) x 64(N=full dh) x 16(K), 256 thr, 8x4 per thread.
// ---------------------------------------------------------------------------
__global__ __launch_bounds__(256) void pv_kernel()
{
    __shared__ __align__(16) float As[16][128];
    __shared__ __align__(16) float Bs[16][64];
    int tid = threadIdx.x;
    int inst = blockIdx.z;
    int row0 = blockIdx.y * 128;
    const float* S = g_S + ((size_t)inst << 20) + ((size_t)row0 << 10);
    const float* V = g_Vp + (size_t)inst * 65536;
    float* O = g_AO + (size_t)inst * 65536 + row0 * 64;
    const float4* st = g_stats + inst * 1024 + row0;
    int ty = tid >> 4, tx = tid & 15;

    uint64_t acc[8][2];
#pragma unroll
    for (int i = 0; i < 8; i++) { acc[i][0] = 0ull; acc[i][1] = 0ull; }

    int i0 = tid * 2;
    int ar0 = i0 >> 2, ac0 = (i0 & 3) * 4;
    int ar1 = (i0 + 1) >> 2, ac1 = ((i0 + 1) & 3) * 4;
    int vr = tid >> 4, vc = (tid & 15) * 4;
    float4 t0 = st[ar0];
    float4 t1 = st[ar1];

    for (int k0 = 0; k0 < 1024; k0 += 16) {
        float4 s0 = *(const float4*)(S + (size_t)ar0 * 1024 + k0 + ac0);
        float4 s1 = *(const float4*)(S + (size_t)ar1 * 1024 + k0 + ac1);
        float4 bv = *(const float4*)(V + (size_t)(k0 + vr) * 64 + vc);
        __syncthreads();
        As[ac0 + 0][ar0] = (s0.x > t0.x) ? __expf(s0.x - t0.y) * t0.z : 0.f;
        As[ac0 + 1][ar0] = (s0.y > t0.x) ? __expf(s0.y - t0.y) * t0.z : 0.f;
        As[ac0 + 2][ar0] = (s0.z > t0.x) ? __expf(s0.z - t0.y) * t0.z : 0.f;
        As[ac0 + 3][ar0] = (s0.w > t0.x) ? __expf(s0.w - t0.y) * t0.z : 0.f;
        As[ac1 + 0][ar1] = (s1.x > t1.x) ? __expf(s1.x - t1.y) * t1.z : 0.f;
        As[ac1 + 1][ar1] = (s1.y > t1.x) ? __expf(s1.y - t1.y) * t1.z : 0.f;
        As[ac1 + 2][ar1] = (s1.z > t1.x) ? __expf(s1.z - t1.y) * t1.z : 0.f;
        As[ac1 + 3][ar1] = (s1.w > t1.x) ? __expf(s1.w - t1.y) * t1.z : 0.f;
        *(float4*)&Bs[vr][vc] = bv;
        __syncthreads();
#pragma unroll
        for (int kk = 0; kk < 16; kk++) {
            float4 a0 = *(const float4*)&As[kk][ty * 8];
            float4 a1 = *(const float4*)&As[kk][ty * 8 + 4];
            ulonglong2 b2 = *(const ulonglong2*)&Bs[kk][tx * 4];
            uint64_t bp0 = b2.x, bp1 = b2.y;
            float af[8] = {a0.x, a0.y, a0.z, a0.w, a1.x, a1.y, a1.z, a1.w};
#pragma unroll
            for (int i = 0; i < 8; i++) {
                uint64_t ap;
                PACK2(ap, __float_as_uint(af[i]));
                FMA2(acc[i][0], ap, bp0, acc[i][0]);
                FMA2(acc[i][1], ap, bp1, acc[i][1]);
            }
        }
    }

#pragma unroll
    for (int i = 0; i < 8; i++) {
        uint32_t l0, h0, l1, h1;
        UNPK2(l0, h0, acc[i][0]);
        UNPK2(l1, h1, acc[i][1]);
        float4 o;
        o.x = __uint_as_float(l0);
        o.y = __uint_as_float(h0);
        o.z = __uint_as_float(l1);
        o.w = __uint_as_float(h1);
        *(float4*)(O + (size_t)(ty * 8 + i) * 64 + tx * 4) = o;
    }
}

// ---------------------------------------------------------------------------
// Kernel 5: final output GEMM: out = AO(8192x512) @ o_w + o_b
// ---------------------------------------------------------------------------
__global__ __launch_bounds__(256) void out_kernel(
    const float* __restrict__ ow, const float* __restrict__ ob,
    float* __restrict__ out)
{
    gemm128x128(g_AO, ow, ob, out, 512, 512);
}

// ---------------------------------------------------------------------------
extern "C" void kernel_launch(void* const* d_in, const int* in_sizes, int n_in,
                              void* d_out, int out_size)
{
    const float* x  = (const float*)d_in[0];
    const float* y  = (const float*)d_in[1];
    const float* qw = (const float*)d_in[2];
    const float* qb = (const float*)d_in[3];
    const float* kw = (const float*)d_in[4];
    const float* kb = (const float*)d_in[5];
    const float* vw = (const float*)d_in[6];
    const float* vb = (const float*)d_in[7];
    const float* ow = (const float*)d_in[8];
    const float* ob = (const float*)d_in[9];
    float* out = (float*)d_out;

    proj_kernel<<<dim3(4, 64, 3), 256>>>(x, y, qw, qb, kw, kb, vw, vb);
    qk_kernel<<<dim3(8, 8, 64), 256>>>();
    stats_kernel<<<65536, 256>>>();
    pv_kernel<<<dim3(1, 8, 64), 256>>>();
    out_kernel<<<dim3(4, 64, 1), 256>>>(ow, ob, out);
}

// round 3
// speedup vs baseline: 1.1854x; 1.1854x over previous
#include <cuda_runtime.h>
#include <cstdint>

// ---------------------------------------------------------------------------
// 64 attention instances: instance i uses contiguous slab [i*65536,(i+1)*65536)
// of each projection viewed as (1024,64). All GEMMs via 3xTF32 mma.sync
// (hi/lo split, 3 MMAs: hh+hl+lh -> ~fp32 accuracy), sm_80+-compatible PTX.
// ---------------------------------------------------------------------------
#define NORMF 0.04419417382415922f   // 1/sqrt(512)

static __device__ float g_Qp[8192 * 512];
static __device__ float g_Kp[8192 * 512];
static __device__ float g_Vp[8192 * 512];
static __device__ float g_AO[8192 * 512];
static __device__ float g_S[67108864];       // 64*1024*1024 scores
static __device__ float4 g_stats[65536];     // per row: mean, max, 1/Z

__device__ __forceinline__ float tf32r(float x) {
    uint32_t u;
    asm("cvt.rna.tf32.f32 %0, %1;" : "=r"(u) : "f"(x));
    return __uint_as_float(u);
}

#define MMA8(d, a, b)                                                          \
    asm volatile("mma.sync.aligned.m16n8k8.row.col.f32.tf32.tf32.f32 "         \
                 "{%0,%1,%2,%3}, {%4,%5,%6,%7}, {%8,%9}, {%0,%1,%2,%3};"       \
                 : "+f"((d)[0]), "+f"((d)[1]), "+f"((d)[2]), "+f"((d)[3])      \
                 : "r"((a)[0]), "r"((a)[1]), "r"((a)[2]), "r"((a)[3]),         \
                   "r"((b)[0]), "r"((b)[1]))

// ---------------------------------------------------------------------------
// Block tile 128x64x16, 256 threads, 8 warps (4m x 2n), warp tile 32x32.
// Smem holds hi/lo planes in FRAGMENT order:
//   A plane: [16 tiles (tk*8+tm)][32 lanes][4 regs]  (2048 floats)
//   B plane: [16 tiles (tk*8+tn)][32 lanes][2 regs]  (1024 floats)
// Stage = AHI|ALO|BHI|BLO = 6144 floats (24KB); 2 stages = 48KB.
// AM: 1 = masked-softmax transform on A load. BT: 0 = B[n][k], 1 = B[k][n].
// EM: 0 = +bias, 1 = *scale, 2 = none.
// ---------------------------------------------------------------------------
template <int AM, int BT, int EM>
__device__ __forceinline__ void mm_body(
    const float* __restrict__ A, int lda,
    const float* __restrict__ B, int ldb,
    const float4* __restrict__ stats,
    const float* __restrict__ bias, float scale,
    float* __restrict__ C, int ldc, int ktot)
{
    extern __shared__ float sm[];
    const int tid = threadIdx.x;
    const int lane = tid & 31, wid = tid >> 5;
    const int wm = wid & 3, wn = wid >> 2;

    // Fill-slot coordinates (2 slots each for A and B; slot = tid + sl*256)
    int tA[2], rA[2], cA[2];   // tile, row-in-tile, col-in-tile
    int tB[2], nB[2], kB[2];
    float4 st0[2], st1[2];
#pragma unroll
    for (int sl = 0; sl < 2; sl++) {
        int slot = tid + sl * 256;
        int tile = slot >> 5, ln = slot & 31;
        tA[sl] = tile; rA[sl] = ln >> 2; cA[sl] = ln & 3;
        tB[sl] = tile; nB[sl] = ln >> 2; kB[sl] = ln & 3;
        if (AM) {
            int m0 = (tile & 7) * 16 + (ln >> 2);
            st0[sl] = stats[m0];
            st1[sl] = stats[m0 + 8];
        }
    }

    float acc[2][4][4];
#pragma unroll
    for (int mt = 0; mt < 2; mt++)
#pragma unroll
        for (int nt = 0; nt < 4; nt++)
#pragma unroll
            for (int e = 0; e < 4; e++) acc[mt][nt][e] = 0.f;

    float ax[2][4];   // staged A gmem values {x00,x10,x01,x11}
    float bx[2][2];   // staged B gmem values {b0,b1}

    auto LDF = [&](int kb) {
#pragma unroll
        for (int sl = 0; sl < 2; sl++) {
            int tm = tA[sl] & 7, tk = tA[sl] >> 3;
            const float* p = A + (size_t)(tm * 16 + rA[sl]) * lda
                               + kb + tk * 8 + cA[sl];
            const float* q = p + 8 * (size_t)lda;
            ax[sl][0] = p[0]; ax[sl][1] = q[0];
            ax[sl][2] = p[4]; ax[sl][3] = q[4];
        }
#pragma unroll
        for (int sl = 0; sl < 2; sl++) {
            int tn = tB[sl] & 7, tk = tB[sl] >> 3;
            int n = tn * 8 + nB[sl];
            int kc = kb + tk * 8 + kB[sl];
            if (BT == 0) {
                const float* p = B + (size_t)n * ldb + kc;
                bx[sl][0] = p[0]; bx[sl][1] = p[4];
            } else {
                const float* p = B + (size_t)kc * ldb + n;
                bx[sl][0] = p[0]; bx[sl][1] = p[4 * (size_t)ldb];
            }
        }
    };

    auto STF = [&](int s) {
        float* base = sm + s * 6144;
#pragma unroll
        for (int sl = 0; sl < 2; sl++) {
            float v0 = ax[sl][0], v1 = ax[sl][1], v2 = ax[sl][2], v3 = ax[sl][3];
            if (AM) {
                v0 = (v0 > st0[sl].x) ? __expf(v0 - st0[sl].y) * st0[sl].z : 0.f;
                v2 = (v2 > st0[sl].x) ? __expf(v2 - st0[sl].y) * st0[sl].z : 0.f;
                v1 = (v1 > st1[sl].x) ? __expf(v1 - st1[sl].y) * st1[sl].z : 0.f;
                v3 = (v3 > st1[sl].x) ? __expf(v3 - st1[sl].y) * st1[sl].z : 0.f;
            }
            float4 h, l;
            h.x = tf32r(v0); l.x = tf32r(v0 - h.x);
            h.y = tf32r(v1); l.y = tf32r(v1 - h.y);
            h.z = tf32r(v2); l.z = tf32r(v2 - h.z);
            h.w = tf32r(v3); l.w = tf32r(v3 - h.w);
            int slot = tid + sl * 256;
            int off = (slot >> 5) * 128 + (slot & 31) * 4;
            *(float4*)(base + off) = h;
            *(float4*)(base + 2048 + off) = l;
        }
#pragma unroll
        for (int sl = 0; sl < 2; sl++) {
            float2 h, l;
            h.x = tf32r(bx[sl][0]); l.x = tf32r(bx[sl][0] - h.x);
            h.y = tf32r(bx[sl][1]); l.y = tf32r(bx[sl][1] - h.y);
            int slot = tid + sl * 256;
            int off = (slot >> 5) * 64 + (slot & 31) * 2;
            *(float2*)(base + 4096 + off) = h;
            *(float2*)(base + 5120 + off) = l;
        }
    };

    auto CMP = [&](int s) {
        const float* base = sm + s * 6144;
#pragma unroll
        for (int tk = 0; tk < 2; tk++) {
            uint4 ah[2], al[2];
            uint2 bh[4], bl[4];
#pragma unroll
            for (int mt = 0; mt < 2; mt++) {
                int tg = tk * 8 + wm * 2 + mt;
                ah[mt] = *(const uint4*)(base + tg * 128 + lane * 4);
                al[mt] = *(const uint4*)(base + 2048 + tg * 128 + lane * 4);
            }
#pragma unroll
            for (int nt = 0; nt < 4; nt++) {
                int tg = tk * 8 + wn * 4 + nt;
                bh[nt] = *(const uint2*)(base + 4096 + tg * 64 + lane * 2);
                bl[nt] = *(const uint2*)(base + 5120 + tg * 64 + lane * 2);
            }
#pragma unroll
            for (int mt = 0; mt < 2; mt++)
#pragma unroll
                for (int nt = 0; nt < 4; nt++) {
                    MMA8(acc[mt][nt], (&ah[mt].x), (&bh[nt].x));
                    MMA8(acc[mt][nt], (&ah[mt].x), (&bl[nt].x));
                    MMA8(acc[mt][nt], (&al[mt].x), (&bh[nt].x));
                }
        }
    };

    const int nk = ktot / 16;
    LDF(0);
    STF(0);
    __syncthreads();
    for (int i = 0; i < nk; i++) {
        if (i + 1 < nk) LDF((i + 1) * 16);   // overlap LDG latency with MMAs
        CMP(i & 1);
        if (i + 1 < nk) STF((i + 1) & 1);
        __syncthreads();
    }

    // Epilogue
#pragma unroll
    for (int mt = 0; mt < 2; mt++)
#pragma unroll
        for (int nt = 0; nt < 4; nt++) {
            int row = wm * 32 + mt * 16 + (lane >> 2);
            int col = wn * 32 + nt * 8 + (lane & 3) * 2;
            float c0 = acc[mt][nt][0], c1 = acc[mt][nt][1];
            float c2 = acc[mt][nt][2], c3 = acc[mt][nt][3];
            if (EM == 0) {
                float b0 = bias[col], b1 = bias[col + 1];
                c0 += b0; c1 += b1; c2 += b0; c3 += b1;
            } else if (EM == 1) {
                c0 *= scale; c1 *= scale; c2 *= scale; c3 *= scale;
            }
            *(float2*)(C + (size_t)row * ldc + col) = make_float2(c0, c1);
            *(float2*)(C + (size_t)(row + 8) * ldc + col) = make_float2(c2, c3);
        }
}

// ------------------------------- kernels -----------------------------------
__global__ void __launch_bounds__(256, 2) proj_mm(
    const float* __restrict__ x, const float* __restrict__ y,
    const float* __restrict__ qw, const float* __restrict__ qb,
    const float* __restrict__ kw, const float* __restrict__ kb,
    const float* __restrict__ vw, const float* __restrict__ vb)
{
    const float* A; const float* W; const float* b; float* Cb;
    if (blockIdx.z == 0)      { A = x; W = qw; b = qb; Cb = g_Qp; }
    else if (blockIdx.z == 1) { A = y; W = kw; b = kb; Cb = g_Kp; }
    else                      { A = y; W = vw; b = vb; Cb = g_Vp; }
    int row0 = blockIdx.y * 128, col0 = blockIdx.x * 64;
    mm_body<0, 1, 0>(A + (size_t)row0 * 512, 512, W + col0, 512, nullptr,
                     b + col0, 1.f, Cb + (size_t)row0 * 512 + col0, 512, 512);
}

__global__ void __launch_bounds__(256, 2) qk_mm()
{
    int inst = blockIdx.z, row0 = blockIdx.y * 128, col0 = blockIdx.x * 64;
    mm_body<0, 0, 1>(g_Qp + (size_t)inst * 65536 + (size_t)row0 * 64, 64,
                     g_Kp + (size_t)inst * 65536 + (size_t)col0 * 64, 64,
                     nullptr, nullptr, NORMF,
                     g_S + ((size_t)inst << 20) + (size_t)row0 * 1024 + col0,
                     1024, 64);
}

__global__ void __launch_bounds__(256, 2) pv_mm()
{
    int inst = blockIdx.z, row0 = blockIdx.y * 128;
    mm_body<1, 1, 2>(g_S + ((size_t)inst << 20) + (size_t)row0 * 1024, 1024,
                     g_Vp + (size_t)inst * 65536, 64,
                     g_stats + inst * 1024 + row0, nullptr, 1.f,
                     g_AO + (size_t)inst * 65536 + (size_t)row0 * 64, 64, 1024);
}

__global__ void __launch_bounds__(256, 2) out_mm(
    const float* __restrict__ ow, const float* __restrict__ ob,
    float* __restrict__ out)
{
    int row0 = blockIdx.y * 128, col0 = blockIdx.x * 64;
    mm_body<0, 1, 0>(g_AO + (size_t)row0 * 512, 512, ow + col0, 512, nullptr,
                     ob + col0, 1.f, out + (size_t)row0 * 512 + col0, 512, 512);
}

// Per-row stats: mean, max, 1/Z with Z = sum_{s>mean} exp(s-max)
__global__ void __launch_bounds__(256) stats_kernel()
{
    int row = blockIdx.x;
    const float4* s = (const float4*)(g_S + ((size_t)row << 10));
    int tid = threadIdx.x;
    float4 v = s[tid];
    float lsum = (v.x + v.y) + (v.z + v.w);
    float lmax = fmaxf(fmaxf(v.x, v.y), fmaxf(v.z, v.w));
#pragma unroll
    for (int o = 16; o; o >>= 1) {
        lsum += __shfl_xor_sync(0xffffffffu, lsum, o);
        lmax = fmaxf(lmax, __shfl_xor_sync(0xffffffffu, lmax, o));
    }
    __shared__ float ssum[8], smaxs[8], szs[8];
    int wid = tid >> 5, lid = tid & 31;
    if (!lid) { ssum[wid] = lsum; smaxs[wid] = lmax; }
    __syncthreads();
    float tsum = 0.f, tmax = -1e30f;
#pragma unroll
    for (int i = 0; i < 8; i++) {
        tsum += ssum[i];
        tmax = fmaxf(tmax, smaxs[i]);
    }
    float mean = tsum * (1.0f / 1024.0f);
    float z = 0.f;
    z += (v.x > mean) ? __expf(v.x - tmax) : 0.f;
    z += (v.y > mean) ? __expf(v.y - tmax) : 0.f;
    z += (v.z > mean) ? __expf(v.z - tmax) : 0.f;
    z += (v.w > mean) ? __expf(v.w - tmax) : 0.f;
#pragma unroll
    for (int o = 16; o; o >>= 1) z += __shfl_xor_sync(0xffffffffu, z, o);
    if (!lid) szs[wid] = z;
    __syncthreads();
    if (!tid) {
        float tz = 0.f;
#pragma unroll
        for (int i = 0; i < 8; i++) tz += szs[i];
        g_stats[row] = make_float4(mean, tmax, 1.0f / tz, 0.f);
    }
}

// ---------------------------------------------------------------------------
extern "C" void kernel_launch(void* const* d_in, const int* in_sizes, int n_in,
                              void* d_out, int out_size)
{
    const float* x  = (const float*)d_in[0];
    const float* y  = (const float*)d_in[1];
    const float* qw = (const float*)d_in[2];
    const float* qb = (const float*)d_in[3];
    const float* kw = (const float*)d_in[4];
    const float* kb = (const float*)d_in[5];
    const float* vw = (const float*)d_in[6];
    const float* vb = (const float*)d_in[7];
    const float* ow = (const float*)d_in[8];
    const float* ob = (const float*)d_in[9];
    float* out = (float*)d_out;

    const int SMB = 49152;  // 2 stages * 24KB
    static int inited = 0;
    if (!inited) {
        cudaFuncSetAttribute(proj_mm, cudaFuncAttributeMaxDynamicSharedMemorySize, SMB);
        cudaFuncSetAttribute(qk_mm,   cudaFuncAttributeMaxDynamicSharedMemorySize, SMB);
        cudaFuncSetAttribute(pv_mm,   cudaFuncAttributeMaxDynamicSharedMemorySize, SMB);
        cudaFuncSetAttribute(out_mm,  cudaFuncAttributeMaxDynamicSharedMemorySize, SMB);
        inited = 1;
    }

    proj_mm<<<dim3(8, 64, 3), 256, SMB>>>(x, y, qw, qb, kw, kb, vw, vb);
    qk_mm<<<dim3(16, 8, 64), 256, SMB>>>();
    stats_kernel<<<65536, 256>>>();
    pv_mm<<<dim3(1, 8, 64), 256, SMB>>>();
    out_mm<<<dim3(8, 64, 1), 256, SMB>>>(ow, ob, out);
}